// round 1
// baseline (speedup 1.0000x reference)
#include <cuda_runtime.h>

// WaterLevelLSTM: B independent LSTM chains, T=5, input=1, H=64.
// out[b] = dot(h_T[b], W_fc) + b_fc
//
// Strategy: fp32-FMA-bound problem (21.5 GMAC recurrent matvec).
// - thread t owns gate row g=t, W_hh row pre-packed in registers as f32x2 pairs
// - tile of NB batch elements' h/c state in SMEM
// - inner matvec uses PTX fma.rn.f32x2 (2x scalar FFMA throughput on sm_103a)
//   with h broadcast-loaded via ld.shared.v2.u64 (conflict-free broadcast)
// - accurate MUFU-based sigmoid/tanh (__expf), NOT tanh.approx (precision)

#define H        64
#define G        256        // 4*H gates
#define TSTEPS   5
#define NB       16         // batch elements per tile
#define NTHREADS 256

typedef unsigned long long u64;

__device__ __forceinline__ u64 fma2(u64 a, u64 b, u64 c) {
    u64 d;
    asm("fma.rn.f32x2 %0, %1, %2, %3;" : "=l"(d) : "l"(a), "l"(b), "l"(c));
    return d;
}
__device__ __forceinline__ u64 add2(u64 a, u64 b) {
    u64 d;
    asm("add.rn.f32x2 %0, %1, %2;" : "=l"(d) : "l"(a), "l"(b));
    return d;
}
__device__ __forceinline__ float2 unpk2(u64 a) {
    float lo, hi;
    asm("mov.b64 {%0,%1}, %2;" : "=f"(lo), "=f"(hi) : "l"(a));
    return make_float2(lo, hi);
}
__device__ __forceinline__ u64 pk2(float lo, float hi) {
    u64 r;
    asm("mov.b64 %0, {%1,%2};" : "=l"(r) : "f"(lo), "f"(hi));
    return r;
}

// accurate fast sigmoid/tanh: MUFU.EX2 (~2^-22 rel) + MUFU.RCP; abs error ~1e-6
__device__ __forceinline__ float sigmoid_f(float x) {
    return __fdividef(1.0f, 1.0f + __expf(-x));
}
__device__ __forceinline__ float tanh_f(float x) {
    return __fdividef(2.0f, 1.0f + __expf(-2.0f * x)) - 1.0f;
}

__global__ __launch_bounds__(NTHREADS, 2)
void lstm_kernel(const float* __restrict__ x,
                 const float* __restrict__ W_ih,
                 const float* __restrict__ W_hh,
                 const float* __restrict__ b_ih,
                 const float* __restrict__ b_hh,
                 const float* __restrict__ W_fc,
                 const float* __restrict__ b_fc,
                 float* __restrict__ out,
                 int B)
{
    __shared__ __align__(16) float h_s[NB][H];   // hidden state, [b][k]
    __shared__ __align__(16) float c_s[NB][H];   // cell state
    __shared__ float g_s[NB][G];                 // gate exchange buffer
    __shared__ float x_s[NB * TSTEPS];
    __shared__ float wfc_s[H];

    const int t = threadIdx.x;          // gate row owned by this thread
    const int gtype = t >> 6;           // 0=i,1=f,2=g,3=o (uniform per warp)

    // ---- per-thread constant weights (loaded once per block) ----
    u64 W2[H / 2];
    {
        const float2* wrow = reinterpret_cast<const float2*>(W_hh + t * H);
#pragma unroll
        for (int k = 0; k < H / 2; k++) {
            float2 v = wrow[k];
            W2[k] = pk2(v.x, v.y);
        }
    }
    const float wih  = W_ih[t];
    const float bias = b_ih[t] + b_hh[t];
    const float bfc  = b_fc[0];
    if (t < H) wfc_s[t] = W_fc[t];

    // ---- grid-stride over batch tiles ----
    for (int tile = blockIdx.x; ; tile += gridDim.x) {
        const int b0 = tile * NB;
        if (b0 >= B) break;

        // zero h/c, stage x for this tile
        for (int i = t; i < NB * H; i += NTHREADS) {
            (&h_s[0][0])[i] = 0.0f;
            (&c_s[0][0])[i] = 0.0f;
        }
        if (t < NB * TSTEPS) {
            int gi = b0 * TSTEPS + t;
            x_s[t] = (gi < B * TSTEPS) ? x[gi] : 0.0f;
        }
        __syncthreads();

#pragma unroll 1
        for (int step = 0; step < TSTEPS; step++) {
            // ---- gate matvec: gate[t] = x*Wih[t] + bias[t] + dot(W_hh[t], h[b]) ----
#pragma unroll 1
            for (int b = 0; b < NB; b++) {
                const ulonglong2* hp =
                    reinterpret_cast<const ulonglong2*>(&h_s[b][0]);
                u64 a0 = 0ull, a1 = 0ull, a2 = 0ull, a3 = 0ull;
#pragma unroll
                for (int k = 0; k < H / 4; k += 2) {
                    ulonglong2 v0 = hp[k];       // broadcast LDS.128 (4 h values)
                    ulonglong2 v1 = hp[k + 1];
                    a0 = fma2(W2[2 * k + 0], v0.x, a0);
                    a1 = fma2(W2[2 * k + 1], v0.y, a1);
                    a2 = fma2(W2[2 * k + 2], v1.x, a2);
                    a3 = fma2(W2[2 * k + 3], v1.y, a3);
                }
                float2 s = unpk2(add2(add2(a0, a1), add2(a2, a3)));
                float gate = fmaf(x_s[b * TSTEPS + step], wih, bias) + s.x + s.y;
                float v = (gtype == 2) ? tanh_f(gate) : sigmoid_f(gate);
                g_s[b][t] = v;
            }
            __syncthreads();

            // ---- state update: each thread handles 4 (b, j) units ----
#pragma unroll
            for (int p = 0; p < (NB * H) / NTHREADS; p++) {
                int idx = t + p * NTHREADS;
                int b = idx >> 6;
                int j = idx & (H - 1);
                float iv = g_s[b][0 * H + j];
                float fv = g_s[b][1 * H + j];
                float gv = g_s[b][2 * H + j];
                float ov = g_s[b][3 * H + j];
                float c  = fmaf(fv, c_s[b][j], iv * gv);
                c_s[b][j] = c;
                h_s[b][j] = ov * tanh_f(c);
            }
            __syncthreads();
        }

        // ---- output head: out[b] = dot(h[b], W_fc) + b_fc ----
        if (t < NB && (b0 + t) < B) {
            float acc = 0.0f;
#pragma unroll
            for (int j = 0; j < H; j++)
                acc = fmaf(h_s[t][j], wfc_s[j], acc);
            out[b0 + t] = acc + bfc;
        }
        __syncthreads();
    }
}

extern "C" void kernel_launch(void* const* d_in, const int* in_sizes, int n_in,
                              void* d_out, int out_size) {
    const float* x    = (const float*)d_in[0];
    const float* W_ih = (const float*)d_in[1];
    const float* W_hh = (const float*)d_in[2];
    const float* b_ih = (const float*)d_in[3];
    const float* b_hh = (const float*)d_in[4];
    const float* W_fc = (const float*)d_in[5];
    const float* b_fc = (const float*)d_in[6];
    float* out = (float*)d_out;

    const int B = in_sizes[0] / TSTEPS;   // x is [B, T, 1]
    int tiles = (B + NB - 1) / NB;
    int grid = tiles < 2048 ? tiles : 2048;

    lstm_kernel<<<grid, NTHREADS>>>(x, W_ih, W_hh, b_ih, b_hh, W_fc, b_fc, out, B);
}